// round 1
// baseline (speedup 1.0000x reference)
#include <cuda_runtime.h>
#include <math.h>

// Problem constants
#define BH 64
#define NSEQ 4096
#define DHEAD 64
#define MFEAT 256
#define DN 0.3535533905932738f   // 64^-0.25
#define HALF_DN2 0.0625f          // 0.5 * 64^-0.5
#define RATIO 0.0625f             // 256^-0.5
#define KEPS 1e-4f
#define K1_CHUNKS 32
#define K2_CHUNKS 8

// Scratch (device globals: allocation-free). All entries fully rewritten each call.
__device__ float g_stab_part[BH * K1_CHUNKS];
__device__ float g_stab[BH];
__device__ float g_ctx_part[(size_t)BH * K2_CHUNKS * MFEAT * DHEAD]; // 33.5 MB
__device__ float g_ksum_part[BH * K2_CHUNKS * MFEAT];
__device__ float g_ctx[(size_t)BH * MFEAT * DHEAD];                  // 4 MB
__device__ float g_ksum[BH * MFEAT];

// ---------------------------------------------------------------------------
// Kernel 1: per-(bh,chunk) max of data_dash_k = DN * (K @ P^T). 128 rows/chunk.
// Thread j owns feature column j (proj row j in registers).
// ---------------------------------------------------------------------------
__global__ __launch_bounds__(256) void k1_stabmax(const float* __restrict__ K,
                                                  const float* __restrict__ P) {
    __shared__ float ksm[32][64];
    __shared__ float red[8];
    const int bh = blockIdx.y, chunk = blockIdx.x, j = threadIdx.x;

    float p[64];
    const float4* pr = (const float4*)(P + j * 64);
    #pragma unroll
    for (int i = 0; i < 16; i++) {
        float4 t = pr[i];
        p[4*i] = t.x; p[4*i+1] = t.y; p[4*i+2] = t.z; p[4*i+3] = t.w;
    }

    const float4* kb = (const float4*)(K + ((size_t)bh * NSEQ + (size_t)chunk * 128) * DHEAD);
    float4* dsm = (float4*)&ksm[0][0];
    float mx = -1e30f;

    for (int st = 0; st < 4; st++) {
        __syncthreads();
        dsm[j]       = kb[st * 512 + j];
        dsm[j + 256] = kb[st * 512 + j + 256];
        __syncthreads();
        #pragma unroll 4
        for (int r = 0; r < 32; r++) {
            float s0 = 0.f, s1 = 0.f, s2 = 0.f, s3 = 0.f;
            #pragma unroll
            for (int d = 0; d < 64; d += 4) {
                s0 = fmaf(ksm[r][d],   p[d],   s0);
                s1 = fmaf(ksm[r][d+1], p[d+1], s1);
                s2 = fmaf(ksm[r][d+2], p[d+2], s2);
                s3 = fmaf(ksm[r][d+3], p[d+3], s3);
            }
            mx = fmaxf(mx, (s0 + s1) + (s2 + s3));
        }
    }
    mx *= DN;  // DN > 0: commutes with max
    #pragma unroll
    for (int o = 16; o; o >>= 1) mx = fmaxf(mx, __shfl_xor_sync(0xffffffffu, mx, o));
    if ((j & 31) == 0) red[j >> 5] = mx;
    __syncthreads();
    if (j == 0) {
        float m2 = red[0];
        #pragma unroll
        for (int w = 1; w < 8; w++) m2 = fmaxf(m2, red[w]);
        g_stab_part[bh * K1_CHUNKS + chunk] = m2;
    }
}

__global__ void k1_reduce() {
    const int t = threadIdx.x;  // t = bh
    float m = g_stab_part[t * K1_CHUNKS];
    #pragma unroll
    for (int c = 1; c < K1_CHUNKS; c++) m = fmaxf(m, g_stab_part[t * K1_CHUNKS + c]);
    g_stab[t] = m;
}

// ---------------------------------------------------------------------------
// Kernel 2: partial context / ksum. Grid (K2_CHUNKS, BH); chunk = 512 rows.
// Thread j owns feature j: accumulates ctx[j][0:64] and ksum[j] in registers.
// ---------------------------------------------------------------------------
__global__ __launch_bounds__(256, 1) void k2_ctx(const float* __restrict__ K,
                                                 const float* __restrict__ V,
                                                 const float* __restrict__ P) {
    __shared__ float ksm[32][64];
    __shared__ float vsm[32][64];
    __shared__ float diag[32];
    const int bh = blockIdx.y, chunk = blockIdx.x, j = threadIdx.x;

    float p[64];
    const float4* pr = (const float4*)(P + j * 64);
    #pragma unroll
    for (int i = 0; i < 16; i++) {
        float4 t = pr[i];
        p[4*i] = t.x; p[4*i+1] = t.y; p[4*i+2] = t.z; p[4*i+3] = t.w;
    }
    const float stab = g_stab[bh];

    float ctx[64];
    #pragma unroll
    for (int e = 0; e < 64; e++) ctx[e] = 0.f;
    float ks = 0.f;

    const float4* kb = (const float4*)(K + ((size_t)bh * NSEQ + (size_t)chunk * 512) * DHEAD);
    const float4* vb = (const float4*)(V + ((size_t)bh * NSEQ + (size_t)chunk * 512) * DHEAD);

    for (int st = 0; st < 16; st++) {
        __syncthreads();
        float4 a0 = kb[st * 512 + j];
        float4 a1 = kb[st * 512 + j + 256];
        ((float4*)&ksm[0][0])[j] = a0;
        ((float4*)&ksm[0][0])[j + 256] = a1;
        ((float4*)&vsm[0][0])[j]       = vb[st * 512 + j];
        ((float4*)&vsm[0][0])[j + 256] = vb[st * 512 + j + 256];
        // diag: thread j's a0 covers row j/16, a1 covers row j/16+16 (4 floats each)
        float ss0 = a0.x*a0.x + a0.y*a0.y + a0.z*a0.z + a0.w*a0.w;
        float ss1 = a1.x*a1.x + a1.y*a1.y + a1.z*a1.z + a1.w*a1.w;
        #pragma unroll
        for (int o = 1; o < 16; o <<= 1) {
            ss0 += __shfl_xor_sync(0xffffffffu, ss0, o);
            ss1 += __shfl_xor_sync(0xffffffffu, ss1, o);
        }
        if ((j & 15) == 0) {
            diag[j >> 4]        = HALF_DN2 * ss0;
            diag[(j >> 4) + 16] = HALF_DN2 * ss1;
        }
        __syncthreads();
        #pragma unroll 2
        for (int r = 0; r < 32; r++) {
            float s0 = 0.f, s1 = 0.f, s2 = 0.f, s3 = 0.f;
            #pragma unroll
            for (int d = 0; d < 64; d += 4) {
                s0 = fmaf(ksm[r][d],   p[d],   s0);
                s1 = fmaf(ksm[r][d+1], p[d+1], s1);
                s2 = fmaf(ksm[r][d+2], p[d+2], s2);
                s3 = fmaf(ksm[r][d+3], p[d+3], s3);
            }
            float dd = DN * ((s0 + s1) + (s2 + s3));
            float kp = RATIO * (__expf(dd - diag[r] - stab) + KEPS);
            ks += kp;
            #pragma unroll
            for (int e = 0; e < 64; e++) ctx[e] = fmaf(kp, vsm[r][e], ctx[e]);
        }
    }

    float* outp = g_ctx_part + (((size_t)bh * K2_CHUNKS + chunk) * MFEAT + j) * DHEAD;
    #pragma unroll
    for (int i = 0; i < 16; i++)
        ((float4*)outp)[i] = make_float4(ctx[4*i], ctx[4*i+1], ctx[4*i+2], ctx[4*i+3]);
    g_ksum_part[(bh * K2_CHUNKS + chunk) * MFEAT + j] = ks;
}

// ---------------------------------------------------------------------------
// Kernel 2r: tree-reduce partial ctx / ksum (deterministic, no atomics).
// ---------------------------------------------------------------------------
__global__ void k2_reduce() {
    const size_t NCTX = (size_t)BH * MFEAT * DHEAD;  // 1048576
    size_t idx = (size_t)blockIdx.x * 256 + threadIdx.x;
    if (idx < NCTX) {
        size_t bh = idx >> 14;
        size_t rem = idx & 16383;
        float s = 0.f;
        #pragma unroll
        for (int c = 0; c < K2_CHUNKS; c++)
            s += g_ctx_part[((bh * K2_CHUNKS + c) << 14) + rem];
        g_ctx[idx] = s;
    } else if (idx < NCTX + (size_t)BH * MFEAT) {
        size_t i2 = idx - NCTX;
        size_t bh = i2 >> 8, j = i2 & 255;
        float s = 0.f;
        #pragma unroll
        for (int c = 0; c < K2_CHUNKS; c++)
            s += g_ksum_part[(bh * K2_CHUNKS + c) * MFEAT + j];
        g_ksum[i2] = s;
    }
}

// ---------------------------------------------------------------------------
// Kernel 3: q-side features + D_inv + output GEMM. Grid (128 tiles, BH);
// tile = 32 rows. Phase A: thread-per-feature dd; Phase B: thread-per-(row,e8).
// ---------------------------------------------------------------------------
__global__ __launch_bounds__(256) void k3_out(const float* __restrict__ Q,
                                              const float* __restrict__ P,
                                              float* __restrict__ O) {
    __shared__ float qsm[32][64];
    __shared__ float dds[32][257];   // padded: dd then overwritten with q'
    __shared__ float ksum_s[256];
    __shared__ float diag[32];
    __shared__ float rmax[32];
    __shared__ float dinv[32];

    const int bh = blockIdx.y, tile = blockIdx.x, t = threadIdx.x;
    const int w = t >> 5, lane = t & 31;

    float p[64];
    {
        const float4* pr = (const float4*)(P + t * 64);
        #pragma unroll
        for (int i = 0; i < 16; i++) {
            float4 tt = pr[i];
            p[4*i] = tt.x; p[4*i+1] = tt.y; p[4*i+2] = tt.z; p[4*i+3] = tt.w;
        }
    }
    ksum_s[t] = g_ksum[bh * MFEAT + t];

    const float4* qb = (const float4*)(Q + ((size_t)bh * NSEQ + (size_t)tile * 32) * DHEAD);
    float4 a0 = qb[t];
    float4 a1 = qb[t + 256];
    ((float4*)&qsm[0][0])[t]       = a0;
    ((float4*)&qsm[0][0])[t + 256] = a1;
    {
        float ss0 = a0.x*a0.x + a0.y*a0.y + a0.z*a0.z + a0.w*a0.w;
        float ss1 = a1.x*a1.x + a1.y*a1.y + a1.z*a1.z + a1.w*a1.w;
        #pragma unroll
        for (int o = 1; o < 16; o <<= 1) {
            ss0 += __shfl_xor_sync(0xffffffffu, ss0, o);
            ss1 += __shfl_xor_sync(0xffffffffu, ss1, o);
        }
        if ((t & 15) == 0) {
            diag[t >> 4]        = HALF_DN2 * ss0;
            diag[(t >> 4) + 16] = HALF_DN2 * ss1;
        }
    }
    __syncthreads();

    // dd[r][j] = DN * dot(q[r], proj[j])
    #pragma unroll 4
    for (int r = 0; r < 32; r++) {
        float s0 = 0.f, s1 = 0.f, s2 = 0.f, s3 = 0.f;
        #pragma unroll
        for (int d = 0; d < 64; d += 4) {
            s0 = fmaf(qsm[r][d],   p[d],   s0);
            s1 = fmaf(qsm[r][d+1], p[d+1], s1);
            s2 = fmaf(qsm[r][d+2], p[d+2], s2);
            s3 = fmaf(qsm[r][d+3], p[d+3], s3);
        }
        dds[r][t] = DN * ((s0 + s1) + (s2 + s3));
    }
    __syncthreads();

    // row max (stab_q, per row)
    #pragma unroll
    for (int rr = 0; rr < 4; rr++) {
        int r = w * 4 + rr;
        float m = dds[r][lane];
        #pragma unroll
        for (int c = 1; c < 8; c++) m = fmaxf(m, dds[r][lane + 32 * c]);
        #pragma unroll
        for (int o = 16; o; o >>= 1) m = fmaxf(m, __shfl_xor_sync(0xffffffffu, m, o));
        if (lane == 0) rmax[r] = m;
    }
    __syncthreads();

    // q' = ratio*(exp(dd - diag - rowmax) + eps), in-place
    #pragma unroll 4
    for (int r = 0; r < 32; r++)
        dds[r][t] = RATIO * (__expf(dds[r][t] - diag[r] - rmax[r]) + KEPS);
    __syncthreads();

    // D_inv[r] = 1 / dot(q'[r], ksum)
    #pragma unroll
    for (int rr = 0; rr < 4; rr++) {
        int r = w * 4 + rr;
        float s = 0.f;
        #pragma unroll
        for (int c = 0; c < 8; c++)
            s = fmaf(dds[r][lane + 32 * c], ksum_s[lane + 32 * c], s);
        #pragma unroll
        for (int o = 16; o; o >>= 1) s += __shfl_xor_sync(0xffffffffu, s, o);
        if (lane == 0) dinv[r] = 1.0f / s;
    }
    __syncthreads();

    // out[r][e] = D_inv[r] * sum_j q'[r][j] * ctx[j][e]
    const int r = t >> 3;
    const int eq = (t & 7) * 2;  // float4 index within row (e0 = eq*4)
    const float4* ctx4 = (const float4*)(g_ctx + (size_t)bh * MFEAT * DHEAD);
    float acc[8];
    #pragma unroll
    for (int i = 0; i < 8; i++) acc[i] = 0.f;
    #pragma unroll 4
    for (int jj = 0; jj < 256; jj++) {
        float qv = dds[r][jj];
        float4 c0 = ctx4[jj * 16 + eq];
        float4 c1 = ctx4[jj * 16 + eq + 1];
        acc[0] = fmaf(qv, c0.x, acc[0]); acc[1] = fmaf(qv, c0.y, acc[1]);
        acc[2] = fmaf(qv, c0.z, acc[2]); acc[3] = fmaf(qv, c0.w, acc[3]);
        acc[4] = fmaf(qv, c1.x, acc[4]); acc[5] = fmaf(qv, c1.y, acc[5]);
        acc[6] = fmaf(qv, c1.z, acc[6]); acc[7] = fmaf(qv, c1.w, acc[7]);
    }
    const float di = dinv[r];
    float* ob = O + ((size_t)bh * NSEQ + (size_t)tile * 32 + r) * DHEAD + (size_t)eq * 4;
    ((float4*)ob)[0] = make_float4(acc[0]*di, acc[1]*di, acc[2]*di, acc[3]*di);
    ((float4*)ob)[1] = make_float4(acc[4]*di, acc[5]*di, acc[6]*di, acc[7]*di);
}

// ---------------------------------------------------------------------------
extern "C" void kernel_launch(void* const* d_in, const int* in_sizes, int n_in,
                              void* d_out, int out_size) {
    const float* q    = (const float*)d_in[0];
    const float* k    = (const float*)d_in[1];
    const float* v    = (const float*)d_in[2];
    const float* proj = (const float*)d_in[3];
    float* out = (float*)d_out;

    k1_stabmax<<<dim3(K1_CHUNKS, BH), 256>>>(k, proj);
    k1_reduce<<<1, BH>>>();
    k2_ctx<<<dim3(K2_CHUNKS, BH), 256>>>(k, v, proj);
    {
        const size_t total = (size_t)BH * MFEAT * DHEAD + (size_t)BH * MFEAT;
        k2_reduce<<<(unsigned)((total + 255) / 256), 256>>>();
    }
    k3_out<<<dim3(NSEQ / 32, BH), 256>>>(q, proj, out);
}

// round 2
// speedup vs baseline: 1.1863x; 1.1863x over previous
#include <cuda_runtime.h>
#include <math.h>

// Problem constants
#define BH 64
#define NSEQ 4096
#define DHEAD 64
#define MFEAT 256
#define DN 0.3535533905932738f   // 64^-0.25
#define HALF_DN2 0.0625f          // 0.5 * 64^-0.5
#define RATIO 0.0625f             // 256^-0.5
#define KEPS 1e-4f
#define K1_CHUNKS 32
#define K2_CHUNKS 8

// Scratch (device globals: allocation-free). All entries fully rewritten each call.
__device__ float g_stab_part[BH * K1_CHUNKS];
__device__ float g_stab[BH];
__device__ float g_ctx_part[(size_t)BH * K2_CHUNKS * MFEAT * DHEAD]; // 33.5 MB
__device__ float g_ksum_part[BH * K2_CHUNKS * MFEAT];
__device__ float g_ctx[(size_t)BH * MFEAT * DHEAD];                  // 4 MB
__device__ float g_ksum[BH * MFEAT];

// ---------------------------------------------------------------------------
// Kernel 1: per-(bh,chunk) max of data_dash_k = DN * (K @ P^T). 128 rows/chunk.
// Thread j owns feature column j (proj row j in registers). LDS.128 dot loop.
// ---------------------------------------------------------------------------
__global__ __launch_bounds__(256) void k1_stabmax(const float* __restrict__ K,
                                                  const float* __restrict__ P) {
    __shared__ float ksm[32][64];
    __shared__ float red[8];
    const int bh = blockIdx.y, chunk = blockIdx.x, j = threadIdx.x;

    float4 p4[16];
    const float4* pr = (const float4*)(P + j * 64);
    #pragma unroll
    for (int i = 0; i < 16; i++) p4[i] = pr[i];

    const float4* kb = (const float4*)(K + ((size_t)bh * NSEQ + (size_t)chunk * 128) * DHEAD);
    float4* dsm = (float4*)&ksm[0][0];
    float mx = -1e30f;

    for (int st = 0; st < 4; st++) {
        __syncthreads();
        dsm[j]       = kb[st * 512 + j];
        dsm[j + 256] = kb[st * 512 + j + 256];
        __syncthreads();
        #pragma unroll 4
        for (int r = 0; r < 32; r++) {
            const float4* krow = (const float4*)ksm[r];
            float s0 = 0.f, s1 = 0.f, s2 = 0.f, s3 = 0.f;
            #pragma unroll
            for (int i = 0; i < 16; i++) {
                float4 kv = krow[i];
                s0 = fmaf(kv.x, p4[i].x, s0);
                s1 = fmaf(kv.y, p4[i].y, s1);
                s2 = fmaf(kv.z, p4[i].z, s2);
                s3 = fmaf(kv.w, p4[i].w, s3);
            }
            mx = fmaxf(mx, (s0 + s1) + (s2 + s3));
        }
    }
    mx *= DN;  // DN > 0: commutes with max
    #pragma unroll
    for (int o = 16; o; o >>= 1) mx = fmaxf(mx, __shfl_xor_sync(0xffffffffu, mx, o));
    if ((j & 31) == 0) red[j >> 5] = mx;
    __syncthreads();
    if (j == 0) {
        float m2 = red[0];
        #pragma unroll
        for (int w = 1; w < 8; w++) m2 = fmaxf(m2, red[w]);
        g_stab_part[bh * K1_CHUNKS + chunk] = m2;
    }
}

__global__ void k1_reduce() {
    const int t = threadIdx.x;  // t = bh
    float m = g_stab_part[t * K1_CHUNKS];
    #pragma unroll
    for (int c = 1; c < K1_CHUNKS; c++) m = fmaxf(m, g_stab_part[t * K1_CHUNKS + c]);
    g_stab[t] = m;
}

// ---------------------------------------------------------------------------
// Kernel 2: partial context / ksum. Grid (K2_CHUNKS, BH); chunk = 512 rows.
// Thread j owns feature j: accumulates ctx[j][0:64] and ksum[j] in registers.
// All shared reads are LDS.128.
// ---------------------------------------------------------------------------
__global__ __launch_bounds__(256, 1) void k2_ctx(const float* __restrict__ K,
                                                 const float* __restrict__ V,
                                                 const float* __restrict__ P) {
    __shared__ float ksm[32][64];
    __shared__ float vsm[32][64];
    __shared__ float diag[32];
    const int bh = blockIdx.y, chunk = blockIdx.x, j = threadIdx.x;

    float4 p4[16];
    const float4* pr = (const float4*)(P + j * 64);
    #pragma unroll
    for (int i = 0; i < 16; i++) p4[i] = pr[i];
    const float stab = g_stab[bh];

    float ctx[64];
    #pragma unroll
    for (int e = 0; e < 64; e++) ctx[e] = 0.f;
    float ks = 0.f;

    const float4* kb = (const float4*)(K + ((size_t)bh * NSEQ + (size_t)chunk * 512) * DHEAD);
    const float4* vb = (const float4*)(V + ((size_t)bh * NSEQ + (size_t)chunk * 512) * DHEAD);

    for (int st = 0; st < 16; st++) {
        __syncthreads();
        float4 a0 = kb[st * 512 + j];
        float4 a1 = kb[st * 512 + j + 256];
        ((float4*)&ksm[0][0])[j] = a0;
        ((float4*)&ksm[0][0])[j + 256] = a1;
        ((float4*)&vsm[0][0])[j]       = vb[st * 512 + j];
        ((float4*)&vsm[0][0])[j + 256] = vb[st * 512 + j + 256];
        // diag: thread j's a0 covers row j/16, a1 covers row j/16+16 (4 floats each)
        float ss0 = a0.x*a0.x + a0.y*a0.y + a0.z*a0.z + a0.w*a0.w;
        float ss1 = a1.x*a1.x + a1.y*a1.y + a1.z*a1.z + a1.w*a1.w;
        #pragma unroll
        for (int o = 1; o < 16; o <<= 1) {
            ss0 += __shfl_xor_sync(0xffffffffu, ss0, o);
            ss1 += __shfl_xor_sync(0xffffffffu, ss1, o);
        }
        if ((j & 15) == 0) {
            diag[j >> 4]        = HALF_DN2 * ss0;
            diag[(j >> 4) + 16] = HALF_DN2 * ss1;
        }
        __syncthreads();
        #pragma unroll 2
        for (int r = 0; r < 32; r++) {
            const float4* krow = (const float4*)ksm[r];
            float s0 = 0.f, s1 = 0.f, s2 = 0.f, s3 = 0.f;
            #pragma unroll
            for (int i = 0; i < 16; i++) {
                float4 kv = krow[i];
                s0 = fmaf(kv.x, p4[i].x, s0);
                s1 = fmaf(kv.y, p4[i].y, s1);
                s2 = fmaf(kv.z, p4[i].z, s2);
                s3 = fmaf(kv.w, p4[i].w, s3);
            }
            float dd = DN * ((s0 + s1) + (s2 + s3));
            float kp = RATIO * (__expf(dd - diag[r] - stab) + KEPS);
            ks += kp;
            const float4* vrow = (const float4*)vsm[r];
            #pragma unroll
            for (int i = 0; i < 16; i++) {
                float4 vv = vrow[i];
                ctx[4*i]   = fmaf(kp, vv.x, ctx[4*i]);
                ctx[4*i+1] = fmaf(kp, vv.y, ctx[4*i+1]);
                ctx[4*i+2] = fmaf(kp, vv.z, ctx[4*i+2]);
                ctx[4*i+3] = fmaf(kp, vv.w, ctx[4*i+3]);
            }
        }
    }

    float* outp = g_ctx_part + (((size_t)bh * K2_CHUNKS + chunk) * MFEAT + j) * DHEAD;
    #pragma unroll
    for (int i = 0; i < 16; i++)
        ((float4*)outp)[i] = make_float4(ctx[4*i], ctx[4*i+1], ctx[4*i+2], ctx[4*i+3]);
    g_ksum_part[(bh * K2_CHUNKS + chunk) * MFEAT + j] = ks;
}

// ---------------------------------------------------------------------------
// Kernel 2r: tree-reduce partial ctx / ksum (deterministic, no atomics).
// ---------------------------------------------------------------------------
__global__ void k2_reduce() {
    const size_t NCTX = (size_t)BH * MFEAT * DHEAD;  // 1048576
    size_t idx = (size_t)blockIdx.x * 256 + threadIdx.x;
    if (idx < NCTX) {
        size_t bh = idx >> 14;
        size_t rem = idx & 16383;
        float s = 0.f;
        #pragma unroll
        for (int c = 0; c < K2_CHUNKS; c++)
            s += g_ctx_part[((bh * K2_CHUNKS + c) << 14) + rem];
        g_ctx[idx] = s;
    } else if (idx < NCTX + (size_t)BH * MFEAT) {
        size_t i2 = idx - NCTX;
        size_t bh = i2 >> 8, j = i2 & 255;
        float s = 0.f;
        #pragma unroll
        for (int c = 0; c < K2_CHUNKS; c++)
            s += g_ksum_part[(bh * K2_CHUNKS + c) * MFEAT + j];
        g_ksum[i2] = s;
    }
}

// ---------------------------------------------------------------------------
// Kernel 3: q-side features + D_inv + output GEMM.
// 64-row tiles, ctx staged in shared, 2 rows per thread in the out-GEMM.
// Dynamic smem: qsm (16KB) + dds (64x257, 65792B) + ctx (64KB) = 147712B.
// ---------------------------------------------------------------------------
#define K3_SMEM_BYTES (16384 + 65792 + 65536)

__global__ __launch_bounds__(256, 1) void k3_out(const float* __restrict__ Q,
                                                 const float* __restrict__ P,
                                                 float* __restrict__ O) {
    extern __shared__ char smraw[];
    float (*qsm)[64]  = (float (*)[64])smraw;                    // [64][64]
    float (*dds)[257] = (float (*)[257])(smraw + 16384);         // [64][257]
    float* ctxs       = (float*)(smraw + 16384 + 65792);         // [256*64]
    __shared__ float ksum_s[256];
    __shared__ float diag[64];
    __shared__ float rmax[64];
    __shared__ float dinv[64];

    const int bh = blockIdx.y, tile = blockIdx.x, t = threadIdx.x;
    const int w = t >> 5, lane = t & 31;

    float4 p4[16];
    {
        const float4* pr = (const float4*)(P + t * 64);
        #pragma unroll
        for (int i = 0; i < 16; i++) p4[i] = pr[i];
    }
    ksum_s[t] = g_ksum[bh * MFEAT + t];

    // Stage ctx for this bh into shared (16 float4 per thread).
    {
        const float4* cg = (const float4*)(g_ctx + (size_t)bh * MFEAT * DHEAD);
        float4* cs = (float4*)ctxs;
        #pragma unroll
        for (int i = 0; i < 16; i++) cs[t + 256 * i] = cg[t + 256 * i];
    }

    // Load Q tile (64 rows x 64) + per-row diag via 16-lane shuffles.
    {
        const float4* qb = (const float4*)(Q + ((size_t)bh * NSEQ + (size_t)tile * 64) * DHEAD);
        float4* qs = (float4*)&qsm[0][0];
        #pragma unroll
        for (int kq = 0; kq < 4; kq++) {
            int i = t + 256 * kq;          // float4 index; row = i >> 4
            float4 a = qb[i];
            qs[i] = a;
            float ss = a.x*a.x + a.y*a.y + a.z*a.z + a.w*a.w;
            #pragma unroll
            for (int o = 1; o < 16; o <<= 1) ss += __shfl_xor_sync(0xffffffffu, ss, o);
            if ((t & 15) == 0) diag[i >> 4] = HALF_DN2 * ss;
        }
    }
    __syncthreads();

    // dd[r][t] = DN * dot(q[r], proj[t])
    #pragma unroll 4
    for (int r = 0; r < 64; r++) {
        const float4* qrow = (const float4*)qsm[r];
        float s0 = 0.f, s1 = 0.f, s2 = 0.f, s3 = 0.f;
        #pragma unroll
        for (int i = 0; i < 16; i++) {
            float4 qv = qrow[i];
            s0 = fmaf(qv.x, p4[i].x, s0);
            s1 = fmaf(qv.y, p4[i].y, s1);
            s2 = fmaf(qv.z, p4[i].z, s2);
            s3 = fmaf(qv.w, p4[i].w, s3);
        }
        dds[r][t] = DN * ((s0 + s1) + (s2 + s3));
    }
    __syncthreads();

    // Per-row max (8 rows per warp).
    #pragma unroll
    for (int rr = 0; rr < 8; rr++) {
        int r = w * 8 + rr;
        float m = dds[r][lane];
        #pragma unroll
        for (int c = 1; c < 8; c++) m = fmaxf(m, dds[r][lane + 32 * c]);
        #pragma unroll
        for (int o = 16; o; o >>= 1) m = fmaxf(m, __shfl_xor_sync(0xffffffffu, m, o));
        if (lane == 0) rmax[r] = m;
    }
    __syncthreads();

    // q' = ratio*(exp(dd - diag - rowmax) + eps), in-place
    #pragma unroll 4
    for (int r = 0; r < 64; r++)
        dds[r][t] = RATIO * (__expf(dds[r][t] - diag[r] - rmax[r]) + KEPS);
    __syncthreads();

    // D_inv[r] = 1 / dot(q'[r], ksum)  (8 rows per warp)
    #pragma unroll
    for (int rr = 0; rr < 8; rr++) {
        int r = w * 8 + rr;
        float s = 0.f;
        #pragma unroll
        for (int c = 0; c < 8; c++)
            s = fmaf(dds[r][lane + 32 * c], ksum_s[lane + 32 * c], s);
        #pragma unroll
        for (int o = 16; o; o >>= 1) s += __shfl_xor_sync(0xffffffffu, s, o);
        if (lane == 0) dinv[r] = 1.0f / s;
    }
    __syncthreads();

    // out[r][e] = D_inv[r] * sum_j q'[r][j] * ctx[j][e]; 2 rows x 8 cols/thread.
    const int rs = t >> 3;           // rows rs and rs+32
    const int eq = (t & 7) * 2;      // float4 index within 64-wide row
    const float4* c4 = (const float4*)ctxs;
    float a0[8], a1[8];
    #pragma unroll
    for (int i = 0; i < 8; i++) { a0[i] = 0.f; a1[i] = 0.f; }
    #pragma unroll 2
    for (int jj = 0; jj < 256; jj++) {
        float4 c0 = c4[jj * 16 + eq];
        float4 c1 = c4[jj * 16 + eq + 1];
        float q0 = dds[rs][jj];
        float q1 = dds[rs + 32][jj];
        a0[0] = fmaf(q0, c0.x, a0[0]); a0[1] = fmaf(q0, c0.y, a0[1]);
        a0[2] = fmaf(q0, c0.z, a0[2]); a0[3] = fmaf(q0, c0.w, a0[3]);
        a0[4] = fmaf(q0, c1.x, a0[4]); a0[5] = fmaf(q0, c1.y, a0[5]);
        a0[6] = fmaf(q0, c1.z, a0[6]); a0[7] = fmaf(q0, c1.w, a0[7]);
        a1[0] = fmaf(q1, c0.x, a1[0]); a1[1] = fmaf(q1, c0.y, a1[1]);
        a1[2] = fmaf(q1, c0.z, a1[2]); a1[3] = fmaf(q1, c0.w, a1[3]);
        a1[4] = fmaf(q1, c1.x, a1[4]); a1[5] = fmaf(q1, c1.y, a1[5]);
        a1[6] = fmaf(q1, c1.z, a1[6]); a1[7] = fmaf(q1, c1.w, a1[7]);
    }
    const float d0 = dinv[rs], d1 = dinv[rs + 32];
    float* ob0 = O + ((size_t)bh * NSEQ + (size_t)tile * 64 + rs) * DHEAD + (size_t)eq * 4;
    float* ob1 = O + ((size_t)bh * NSEQ + (size_t)tile * 64 + rs + 32) * DHEAD + (size_t)eq * 4;
    ((float4*)ob0)[0] = make_float4(a0[0]*d0, a0[1]*d0, a0[2]*d0, a0[3]*d0);
    ((float4*)ob0)[1] = make_float4(a0[4]*d0, a0[5]*d0, a0[6]*d0, a0[7]*d0);
    ((float4*)ob1)[0] = make_float4(a1[0]*d1, a1[1]*d1, a1[2]*d1, a1[3]*d1);
    ((float4*)ob1)[1] = make_float4(a1[4]*d1, a1[5]*d1, a1[6]*d1, a1[7]*d1);
}

// ---------------------------------------------------------------------------
extern "C" void kernel_launch(void* const* d_in, const int* in_sizes, int n_in,
                              void* d_out, int out_size) {
    const float* q    = (const float*)d_in[0];
    const float* k    = (const float*)d_in[1];
    const float* v    = (const float*)d_in[2];
    const float* proj = (const float*)d_in[3];
    float* out = (float*)d_out;

    cudaFuncSetAttribute(k3_out, cudaFuncAttributeMaxDynamicSharedMemorySize,
                         K3_SMEM_BYTES);

    k1_stabmax<<<dim3(K1_CHUNKS, BH), 256>>>(k, proj);
    k1_reduce<<<1, BH>>>();
    k2_ctx<<<dim3(K2_CHUNKS, BH), 256>>>(k, v, proj);
    {
        const size_t total = (size_t)BH * MFEAT * DHEAD + (size_t)BH * MFEAT;
        k2_reduce<<<(unsigned)((total + 255) / 256), 256>>>();
    }
    k3_out<<<dim3(NSEQ / 64, BH), 256, K3_SMEM_BYTES>>>(q, proj, out);
}

// round 4
// speedup vs baseline: 1.7147x; 1.4455x over previous
#include <cuda_runtime.h>
#include <math.h>

// Problem constants
#define BH 64
#define NSEQ 4096
#define DHEAD 64
#define MFEAT 256
#define DN 0.3535533905932738f   // 64^-0.25
#define HALF_DN2 0.0625f          // 0.5 * 64^-0.5
#define RATIO 0.0625f             // 256^-0.5
#define KEPS 1e-4f
#define K1_CHUNKS 32
#define K2_CHUNKS 8

typedef unsigned long long u64;

// Packed fp32x2 helpers (sm_103a FFMA2 path)
__device__ __forceinline__ u64 ffma2(u64 a, u64 b, u64 c) {
    u64 d;
    asm("fma.rn.f32x2 %0, %1, %2, %3;" : "=l"(d) : "l"(a), "l"(b), "l"(c));
    return d;
}
__device__ __forceinline__ u64 fmul2(u64 a, u64 b) {
    u64 d;
    asm("mul.rn.f32x2 %0, %1, %2;" : "=l"(d) : "l"(a), "l"(b));
    return d;
}
__device__ __forceinline__ u64 pack2(float lo, float hi) {
    u64 d; asm("mov.b64 %0, {%1, %2};" : "=l"(d) : "f"(lo), "f"(hi)); return d;
}
__device__ __forceinline__ float2 unpack2(u64 v) {
    float lo, hi; asm("mov.b64 {%0, %1}, %2;" : "=f"(lo), "=f"(hi) : "l"(v));
    return make_float2(lo, hi);
}

// Scratch (device globals: allocation-free). All entries fully rewritten each call.
__device__ float g_stab_part[BH * K1_CHUNKS];
__device__ float g_stab[BH];
__device__ float g_dd[(size_t)BH * NSEQ * MFEAT];                    // 268 MB
__device__ float g_diag[BH * NSEQ];                                  // 1 MB
__device__ float g_ctx_part[(size_t)BH * K2_CHUNKS * MFEAT * DHEAD]; // 33.5 MB
__device__ float g_ksum_part[BH * K2_CHUNKS * MFEAT];
__device__ float g_ctx[(size_t)BH * MFEAT * DHEAD];                  // 4 MB
__device__ float g_ksum[BH * MFEAT];

// ---------------------------------------------------------------------------
// Kernel 1: dd_k = DN * (K @ P^T), stored to g_dd; per-(bh,chunk) max;
// diag_k stored to g_diag. 128 rows per chunk, FFMA2 dot products.
// ---------------------------------------------------------------------------
__global__ __launch_bounds__(256) void k1_stabmax(const float* __restrict__ K,
                                                  const float* __restrict__ P) {
    __shared__ __align__(16) float ksm[32][64];
    __shared__ float red[8];
    const int bh = blockIdx.y, chunk = blockIdx.x, j = threadIdx.x;

    u64 p2[32];
    {
        const ulonglong2* pr = (const ulonglong2*)(P + j * 64);
        #pragma unroll
        for (int i = 0; i < 16; i++) { ulonglong2 t = pr[i]; p2[2*i] = t.x; p2[2*i+1] = t.y; }
    }

    const float4* kb = (const float4*)(K + ((size_t)bh * NSEQ + (size_t)chunk * 128) * DHEAD);
    float* ddb = g_dd + ((size_t)bh * NSEQ + (size_t)chunk * 128) * MFEAT;
    float* diagb = g_diag + bh * NSEQ + chunk * 128;
    float4* dsm = (float4*)&ksm[0][0];
    float mx = -1e30f;

    for (int st = 0; st < 4; st++) {
        __syncthreads();
        float4 a0 = kb[st * 512 + j];
        float4 a1 = kb[st * 512 + j + 256];
        dsm[j]       = a0;
        dsm[j + 256] = a1;
        float ss0 = a0.x*a0.x + a0.y*a0.y + a0.z*a0.z + a0.w*a0.w;
        float ss1 = a1.x*a1.x + a1.y*a1.y + a1.z*a1.z + a1.w*a1.w;
        #pragma unroll
        for (int o = 1; o < 16; o <<= 1) {
            ss0 += __shfl_xor_sync(0xffffffffu, ss0, o);
            ss1 += __shfl_xor_sync(0xffffffffu, ss1, o);
        }
        if ((j & 15) == 0) {
            diagb[st * 32 + (j >> 4)]      = HALF_DN2 * ss0;
            diagb[st * 32 + (j >> 4) + 16] = HALF_DN2 * ss1;
        }
        __syncthreads();
        #pragma unroll 4
        for (int r = 0; r < 32; r++) {
            const ulonglong2* krow = (const ulonglong2*)ksm[r];
            u64 acc0 = 0, acc1 = 0, acc2 = 0, acc3 = 0;
            #pragma unroll
            for (int i = 0; i < 8; i++) {
                ulonglong2 kva = krow[2*i];
                ulonglong2 kvb = krow[2*i+1];
                acc0 = ffma2(kva.x, p2[4*i],   acc0);
                acc1 = ffma2(kva.y, p2[4*i+1], acc1);
                acc2 = ffma2(kvb.x, p2[4*i+2], acc2);
                acc3 = ffma2(kvb.y, p2[4*i+3], acc3);
            }
            float2 f0 = unpack2(acc0), f1 = unpack2(acc1);
            float2 f2 = unpack2(acc2), f3 = unpack2(acc3);
            float s = ((f0.x + f0.y) + (f1.x + f1.y)) + ((f2.x + f2.y) + (f3.x + f3.y));
            float dd = DN * s;
            ddb[(st * 32 + r) * MFEAT + j] = dd;
            mx = fmaxf(mx, dd);
        }
    }
    #pragma unroll
    for (int o = 16; o; o >>= 1) mx = fmaxf(mx, __shfl_xor_sync(0xffffffffu, mx, o));
    if ((j & 31) == 0) red[j >> 5] = mx;
    __syncthreads();
    if (j == 0) {
        float m2 = red[0];
        #pragma unroll
        for (int w = 1; w < 8; w++) m2 = fmaxf(m2, red[w]);
        g_stab_part[bh * K1_CHUNKS + chunk] = m2;
    }
}

__global__ void k1_reduce() {
    const int t = threadIdx.x;  // t = bh
    float m = g_stab_part[t * K1_CHUNKS];
    #pragma unroll
    for (int c = 1; c < K1_CHUNKS; c++) m = fmaxf(m, g_stab_part[t * K1_CHUNKS + c]);
    g_stab[t] = m;
}

// ---------------------------------------------------------------------------
// Kernel 2: k' from staged dd (no K, no proj), partial ctx/ksum via FFMA2.
// Grid (K2_CHUNKS, BH); chunk = 512 rows, 16 stages of 32 rows.
// ---------------------------------------------------------------------------
__global__ __launch_bounds__(256) void k2_ctx(const float* __restrict__ V) {
    __shared__ __align__(16) float dds[32][256];   // 32KB
    __shared__ __align__(16) float vsm[32][64];    // 8KB
    __shared__ float diag_s[512];                  // 2KB
    const int bh = blockIdx.y, chunk = blockIdx.x, j = threadIdx.x;

    diag_s[j]       = g_diag[bh * NSEQ + chunk * 512 + j];
    diag_s[j + 256] = g_diag[bh * NSEQ + chunk * 512 + j + 256];
    const float stab = g_stab[bh];

    u64 ctx2[32];
    #pragma unroll
    for (int i = 0; i < 32; i++) ctx2[i] = 0ull;
    float ks = 0.f;

    const float4* ddg = (const float4*)(g_dd + ((size_t)bh * NSEQ + (size_t)chunk * 512) * MFEAT);
    const float4* vb  = (const float4*)(V + ((size_t)bh * NSEQ + (size_t)chunk * 512) * DHEAD);

    for (int st = 0; st < 16; st++) {
        __syncthreads();
        #pragma unroll
        for (int q = 0; q < 8; q++)
            ((float4*)&dds[0][0])[j + 256 * q] = ddg[st * 2048 + j + 256 * q];
        ((float4*)&vsm[0][0])[j]       = vb[st * 512 + j];
        ((float4*)&vsm[0][0])[j + 256] = vb[st * 512 + j + 256];
        __syncthreads();
        #pragma unroll 2
        for (int r = 0; r < 32; r++) {
            float dd = dds[r][j];
            float kp = RATIO * (__expf(dd - diag_s[st * 32 + r] - stab) + KEPS);
            ks += kp;
            u64 kp2 = pack2(kp, kp);
            const ulonglong2* vrow = (const ulonglong2*)vsm[r];
            #pragma unroll
            for (int i = 0; i < 16; i++) {
                ulonglong2 vv = vrow[i];
                ctx2[2*i]   = ffma2(kp2, vv.x, ctx2[2*i]);
                ctx2[2*i+1] = ffma2(kp2, vv.y, ctx2[2*i+1]);
            }
        }
    }

    ulonglong2* outp = (ulonglong2*)(g_ctx_part +
        (((size_t)bh * K2_CHUNKS + chunk) * MFEAT + j) * DHEAD);
    #pragma unroll
    for (int i = 0; i < 16; i++)
        outp[i] = make_ulonglong2(ctx2[2*i], ctx2[2*i+1]);
    g_ksum_part[(bh * K2_CHUNKS + chunk) * MFEAT + j] = ks;
}

// ---------------------------------------------------------------------------
// Kernel 2r: tree-reduce partial ctx / ksum (deterministic, no atomics).
// ---------------------------------------------------------------------------
__global__ void k2_reduce() {
    const size_t NCTX = (size_t)BH * MFEAT * DHEAD;  // 1048576
    size_t idx = (size_t)blockIdx.x * 256 + threadIdx.x;
    if (idx < NCTX) {
        size_t bh = idx >> 14;
        size_t rem = idx & 16383;
        float s = 0.f;
        #pragma unroll
        for (int c = 0; c < K2_CHUNKS; c++)
            s += g_ctx_part[((bh * K2_CHUNKS + c) << 14) + rem];
        g_ctx[idx] = s;
    } else if (idx < NCTX + (size_t)BH * MFEAT) {
        size_t i2 = idx - NCTX;
        size_t bh = i2 >> 8, j = i2 & 255;
        float s = 0.f;
        #pragma unroll
        for (int c = 0; c < K2_CHUNKS; c++)
            s += g_ksum_part[(bh * K2_CHUNKS + c) * MFEAT + j];
        g_ksum[i2] = s;
    }
}

// ---------------------------------------------------------------------------
// Kernel 3: q-side features + D_inv + output GEMM, 128-row tiles, FFMA2.
// Dynamic smem: dds [128][257] (131584B) + overlay (qsm 32KB then ctx 64KB).
// ---------------------------------------------------------------------------
#define K3_SMEM_BYTES (131584 + 65536)

__global__ __launch_bounds__(256, 1) void k3_out(const float* __restrict__ Q,
                                                 const float* __restrict__ P,
                                                 float* __restrict__ O) {
    extern __shared__ __align__(16) char smraw[];
    float (*dds)[257] = (float (*)[257])smraw;            // [128][257]
    float* ovl  = (float*)(smraw + 131584);               // 64KB overlay
    float (*qsm)[64] = (float (*)[64])ovl;                // phase 1-2: Q tile
    float* ctxs = ovl;                                    // phase 3+: ctx
    __shared__ float ksum_s[256];
    __shared__ float diag[128];
    __shared__ float rmax[128];
    __shared__ float dinv[128];

    const int bh = blockIdx.y, tile = blockIdx.x, t = threadIdx.x;
    const int w = t >> 5, lane = t & 31;

    u64 p2[32];
    {
        const ulonglong2* pr = (const ulonglong2*)(P + t * 64);
        #pragma unroll
        for (int i = 0; i < 16; i++) { ulonglong2 tt = pr[i]; p2[2*i] = tt.x; p2[2*i+1] = tt.y; }
    }
    ksum_s[t] = g_ksum[bh * MFEAT + t];

    // Load Q tile (128 x 64) + per-row diag via 16-lane shuffles.
    {
        const float4* qb = (const float4*)(Q + ((size_t)bh * NSEQ + (size_t)tile * 128) * DHEAD);
        float4* qs = (float4*)&qsm[0][0];
        #pragma unroll
        for (int kq = 0; kq < 8; kq++) {
            int i = t + 256 * kq;          // float4 index; row = i >> 4
            float4 a = qb[i];
            qs[i] = a;
            float ss = a.x*a.x + a.y*a.y + a.z*a.z + a.w*a.w;
            #pragma unroll
            for (int o = 1; o < 16; o <<= 1) ss += __shfl_xor_sync(0xffffffffu, ss, o);
            if ((t & 15) == 0) diag[i >> 4] = HALF_DN2 * ss;
        }
    }
    __syncthreads();

    // dd[r][t] = DN * dot(q[r], proj[t])   (FFMA2)
    #pragma unroll 2
    for (int r = 0; r < 128; r++) {
        const ulonglong2* qrow = (const ulonglong2*)qsm[r];
        u64 acc0 = 0, acc1 = 0, acc2 = 0, acc3 = 0;
        #pragma unroll
        for (int i = 0; i < 8; i++) {
            ulonglong2 qa = qrow[2*i];
            ulonglong2 qb2 = qrow[2*i+1];
            acc0 = ffma2(qa.x,  p2[4*i],   acc0);
            acc1 = ffma2(qa.y,  p2[4*i+1], acc1);
            acc2 = ffma2(qb2.x, p2[4*i+2], acc2);
            acc3 = ffma2(qb2.y, p2[4*i+3], acc3);
        }
        float2 f0 = unpack2(acc0), f1 = unpack2(acc1);
        float2 f2 = unpack2(acc2), f3 = unpack2(acc3);
        float s = ((f0.x + f0.y) + (f1.x + f1.y)) + ((f2.x + f2.y) + (f3.x + f3.y));
        dds[r][t] = DN * s;
    }
    __syncthreads();

    // ctx load into overlay (qsm dead now); overlaps the reduction phases.
    {
        const float4* cg = (const float4*)(g_ctx + (size_t)bh * MFEAT * DHEAD);
        float4* cs = (float4*)ctxs;
        #pragma unroll
        for (int i = 0; i < 16; i++) cs[t + 256 * i] = cg[t + 256 * i];
    }

    // Per-row max (16 rows per warp).
    #pragma unroll
    for (int rr = 0; rr < 16; rr++) {
        int r = w * 16 + rr;
        float m = dds[r][lane];
        #pragma unroll
        for (int c = 1; c < 8; c++) m = fmaxf(m, dds[r][lane + 32 * c]);
        #pragma unroll
        for (int o = 16; o; o >>= 1) m = fmaxf(m, __shfl_xor_sync(0xffffffffu, m, o));
        if (lane == 0) rmax[r] = m;
    }
    __syncthreads();

    // q' = ratio*(exp(dd - diag - rowmax) + eps), in-place
    #pragma unroll 4
    for (int r = 0; r < 128; r++)
        dds[r][t] = RATIO * (__expf(dds[r][t] - diag[r] - rmax[r]) + KEPS);
    __syncthreads();

    // D_inv[r] = 1 / dot(q'[r], ksum)  (16 rows per warp)
    #pragma unroll
    for (int rr = 0; rr < 16; rr++) {
        int r = w * 16 + rr;
        float s = 0.f;
        #pragma unroll
        for (int c = 0; c < 8; c++)
            s = fmaf(dds[r][lane + 32 * c], ksum_s[lane + 32 * c], s);
        #pragma unroll
        for (int o = 16; o; o >>= 1) s += __shfl_xor_sync(0xffffffffu, s, o);
        if (lane == 0) dinv[r] = 1.0f / s;
    }
    __syncthreads();

    // out[r][e]: 4 rows x 8 cols per thread via FFMA2.
    const int rs = t >> 3;           // rows rs, rs+32, rs+64, rs+96
    const int ecg = (t & 7) * 2;     // ulonglong2 index within 64-float row
    const ulonglong2* cc = (const ulonglong2*)ctxs;
    u64 a0[4], a1[4], a2[4], a3[4];
    #pragma unroll
    for (int i = 0; i < 4; i++) { a0[i]=0; a1[i]=0; a2[i]=0; a3[i]=0; }
    #pragma unroll 2
    for (int jj = 0; jj < 256; jj++) {
        ulonglong2 cA = cc[jj * 16 + ecg];
        ulonglong2 cB = cc[jj * 16 + ecg + 1];
        float v0 = dds[rs][jj];
        float v1 = dds[rs + 32][jj];
        float v2 = dds[rs + 64][jj];
        float v3 = dds[rs + 96][jj];
        u64 q0 = pack2(v0, v0), q1 = pack2(v1, v1);
        u64 q2 = pack2(v2, v2), q3 = pack2(v3, v3);
        a0[0] = ffma2(q0, cA.x, a0[0]); a0[1] = ffma2(q0, cA.y, a0[1]);
        a0[2] = ffma2(q0, cB.x, a0[2]); a0[3] = ffma2(q0, cB.y, a0[3]);
        a1[0] = ffma2(q1, cA.x, a1[0]); a1[1] = ffma2(q1, cA.y, a1[1]);
        a1[2] = ffma2(q1, cB.x, a1[2]); a1[3] = ffma2(q1, cB.y, a1[3]);
        a2[0] = ffma2(q2, cA.x, a2[0]); a2[1] = ffma2(q2, cA.y, a2[1]);
        a2[2] = ffma2(q2, cB.x, a2[2]); a2[3] = ffma2(q2, cB.y, a2[3]);
        a3[0] = ffma2(q3, cA.x, a3[0]); a3[1] = ffma2(q3, cA.y, a3[1]);
        a3[2] = ffma2(q3, cB.x, a3[2]); a3[3] = ffma2(q3, cB.y, a3[3]);
    }
    // Column offset in floats = ecg * 4 (one ulonglong2 = 4 floats).
    float* obase = O + ((size_t)bh * NSEQ + (size_t)tile * 128) * DHEAD + (size_t)ecg * 4;
    {
        u64 d2;
        d2 = pack2(dinv[rs], dinv[rs]);
        ((ulonglong2*)(obase + (size_t)rs * 64))[0] = make_ulonglong2(fmul2(a0[0], d2), fmul2(a0[1], d2));
        ((ulonglong2*)(obase + (size_t)rs * 64))[1] = make_ulonglong2(fmul2(a0[2], d2), fmul2(a0[3], d2));
        d2 = pack2(dinv[rs + 32], dinv[rs + 32]);
        ((ulonglong2*)(obase + (size_t)(rs + 32) * 64))[0] = make_ulonglong2(fmul2(a1[0], d2), fmul2(a1[1], d2));
        ((ulonglong2*)(obase + (size_t)(rs + 32) * 64))[1] = make_ulonglong2(fmul2(a1[2], d2), fmul2(a1[3], d2));
        d2 = pack2(dinv[rs + 64], dinv[rs + 64]);
        ((ulonglong2*)(obase + (size_t)(rs + 64) * 64))[0] = make_ulonglong2(fmul2(a2[0], d2), fmul2(a2[1], d2));
        ((ulonglong2*)(obase + (size_t)(rs + 64) * 64))[1] = make_ulonglong2(fmul2(a2[2], d2), fmul2(a2[3], d2));
        d2 = pack2(dinv[rs + 96], dinv[rs + 96]);
        ((ulonglong2*)(obase + (size_t)(rs + 96) * 64))[0] = make_ulonglong2(fmul2(a3[0], d2), fmul2(a3[1], d2));
        ((ulonglong2*)(obase + (size_t)(rs + 96) * 64))[1] = make_ulonglong2(fmul2(a3[2], d2), fmul2(a3[3], d2));
    }
}

// ---------------------------------------------------------------------------
extern "C" void kernel_launch(void* const* d_in, const int* in_sizes, int n_in,
                              void* d_out, int out_size) {
    const float* q    = (const float*)d_in[0];
    const float* k    = (const float*)d_in[1];
    const float* v    = (const float*)d_in[2];
    const float* proj = (const float*)d_in[3];
    float* out = (float*)d_out;

    cudaFuncSetAttribute(k3_out, cudaFuncAttributeMaxDynamicSharedMemorySize,
                         K3_SMEM_BYTES);

    k1_stabmax<<<dim3(K1_CHUNKS, BH), 256>>>(k, proj);
    k1_reduce<<<1, BH>>>();
    k2_ctx<<<dim3(K2_CHUNKS, BH), 256>>>(v);
    {
        const size_t total = (size_t)BH * MFEAT * DHEAD + (size_t)BH * MFEAT;
        k2_reduce<<<(unsigned)((total + 255) / 256), 256>>>();
    }
    k3_out<<<dim3(NSEQ / 128, BH), 256, K3_SMEM_BYTES>>>(q, proj, out);
}